// round 11
// baseline (speedup 1.0000x reference)
#include <cuda_runtime.h>

#define NN 50000
#define EE 800000
#define NEG 0.2f
#define EPSV 1e-5f
#define L2E 1.4426950408889634f
#define AGG_BLOCKS 6250

// ---- scratch (static __device__, no allocations) ----
__device__ float g_xl[NN * 128];
__device__ float g_xr[NN * 128];
__device__ float g_y[NN * 64];
__device__ int   g_cnt[NN];
__device__ int   g_wofs[NN];
__device__ int   g_rowptr[NN + 1];
__device__ int   g_csrsrc[EE];
__device__ float g_sum[64];
__device__ float g_sumsq[64];
__device__ float g_nA[64];
__device__ float g_nB[64];
__device__ int   g_done;          // zero-init at load; self-resetting per agg launch

// ---------------- CSR build ----------------
__global__ void k_zero_all() {
    int i = blockIdx.x * blockDim.x + threadIdx.x;
    if (i < NN) g_cnt[i] = 0;
    if (i < 64) { g_sum[i] = 0.f; g_sumsq[i] = 0.f; }
}

// stitched: blocks [0, 3125) do the dst histogram; blocks [3125, 9375) do layer-1 GEMM
__global__ void k_hist_gemm3(const int* __restrict__ dst,
                             const float* __restrict__ x,
                             const float* __restrict__ Wl,
                             const float* __restrict__ Wr) {
    if (blockIdx.x < 3125) {
        int e = blockIdx.x * 256 + threadIdx.x;
        if (e < EE) atomicAdd(&g_cnt[dst[e]], 1);
    } else {
        int t = (blockIdx.x - 3125) * 256 + threadIdx.x;
        int row = t >> 5, q = t & 31;
        if (row >= NN) return;
        float x0 = __ldg(&x[row * 3 + 0]);
        float x1 = __ldg(&x[row * 3 + 1]);
        float x2 = __ldg(&x[row * 3 + 2]);
        const float4* Wl4 = (const float4*)Wl;
        const float4* Wr4 = (const float4*)Wr;
        float4 a = __ldg(&Wl4[q]), b = __ldg(&Wl4[32 + q]), c = __ldg(&Wl4[64 + q]);
        float4 o;
        o.x = x0 * a.x + x1 * b.x + x2 * c.x;
        o.y = x0 * a.y + x1 * b.y + x2 * c.y;
        o.z = x0 * a.z + x1 * b.z + x2 * c.z;
        o.w = x0 * a.w + x1 * b.w + x2 * c.w;
        ((float4*)g_xl)[row * 32 + q] = o;
        a = __ldg(&Wr4[q]); b = __ldg(&Wr4[32 + q]); c = __ldg(&Wr4[64 + q]);
        o.x = x0 * a.x + x1 * b.x + x2 * c.x;
        o.y = x0 * a.y + x1 * b.y + x2 * c.y;
        o.z = x0 * a.z + x1 * b.z + x2 * c.z;
        o.w = x0 * a.w + x1 * b.w + x2 * c.w;
        ((float4*)g_xr)[row * 32 + q] = o;
    }
}

__global__ void k_scan() {
    __shared__ int sT[1024];
    int tid = threadIdx.x;
    const int CH = (NN + 1023) / 1024;
    int base = tid * CH;
    int s = 0;
    for (int i = 0; i < CH; i++) {
        int idx = base + i;
        s += (idx < NN) ? g_cnt[idx] : 0;
    }
    sT[tid] = s;
    __syncthreads();
    for (int off = 1; off < 1024; off <<= 1) {
        int v = (tid >= off) ? sT[tid - off] : 0;
        __syncthreads();
        sT[tid] += v;
        __syncthreads();
    }
    int run = (tid == 0) ? 0 : sT[tid - 1];
    for (int i = 0; i < CH; i++) {
        int idx = base + i;
        if (idx < NN) {
            g_rowptr[idx] = run;
            g_wofs[idx]   = run;
            run += g_cnt[idx];
        }
    }
    if (tid == 1023) g_rowptr[NN] = run;
}

// ILP-4 scatter: 4 independent atomic->store chains per thread
__global__ void k_scatter(const int* __restrict__ src, const int* __restrict__ dst) {
    int e = (blockIdx.x * blockDim.x + threadIdx.x) * 4;
    if (e + 3 < EE) {
        int4 d = *(const int4*)&dst[e];
        int4 s = *(const int4*)&src[e];
        int p0 = atomicAdd(&g_wofs[d.x], 1);
        int p1 = atomicAdd(&g_wofs[d.y], 1);
        int p2 = atomicAdd(&g_wofs[d.z], 1);
        int p3 = atomicAdd(&g_wofs[d.w], 1);
        g_csrsrc[p0] = s.x;
        g_csrsrc[p1] = s.y;
        g_csrsrc[p2] = s.z;
        g_csrsrc[p3] = s.w;
    } else {
        for (int k = e; k < EE; k++) {
            int p = atomicAdd(&g_wofs[dst[k]], 1);
            g_csrsrc[p] = src[k];
        }
    }
}

// ---------------- layers 2/3 dual GEMM, 128-row tiles, fused GraphNorm+ReLU ----------------
__global__ void k_gemm64(const float* __restrict__ W_l, const float* __restrict__ W_r) {
    __shared__ float As[128][68];
    __shared__ float Ws[64][64];
    int by = blockIdx.y;
    const float* W = (by < 2) ? W_l : W_r;
    float* Cp = (by < 2) ? g_xl : g_xr;
    int colbase = (by & 1) * 64;
    int row0 = blockIdx.x * 128;
    int tid = threadIdx.x;  // 256

    for (int i = tid; i < 128 * 16; i += 256) {
        int r = i >> 4, k4 = (i & 15) * 4;
        float4 v = make_float4(0.f, 0.f, 0.f, 0.f);
        if (row0 + r < NN) v = ((const float4*)g_y)[(row0 + r) * 16 + (k4 >> 2)];
        v.x = fmaxf(v.x * g_nA[k4 + 0] + g_nB[k4 + 0], 0.f);
        v.y = fmaxf(v.y * g_nA[k4 + 1] + g_nB[k4 + 1], 0.f);
        v.z = fmaxf(v.z * g_nA[k4 + 2] + g_nB[k4 + 2], 0.f);
        v.w = fmaxf(v.w * g_nA[k4 + 3] + g_nB[k4 + 3], 0.f);
        *(float4*)&As[r][k4] = v;
    }
    for (int i = tid; i < 64 * 16; i += 256) {
        int k = i >> 4, c4 = i & 15;
        *(float4*)&Ws[k][c4 * 4] = __ldg((const float4*)(W + k * 128 + colbase + c4 * 4));
    }
    __syncthreads();

    int tx = tid & 15, ty = tid >> 4;   // 8 rows x 4 cols per thread
    float acc[8][4];
#pragma unroll
    for (int i = 0; i < 8; i++)
#pragma unroll
        for (int j = 0; j < 4; j++) acc[i][j] = 0.f;

#pragma unroll 4
    for (int k = 0; k < 64; k++) {
        float4 wv = *(float4*)&Ws[k][tx * 4];
        float a[8];
#pragma unroll
        for (int i = 0; i < 8; i++) a[i] = As[ty * 8 + i][k];
#pragma unroll
        for (int i = 0; i < 8; i++) {
            acc[i][0] += a[i] * wv.x;
            acc[i][1] += a[i] * wv.y;
            acc[i][2] += a[i] * wv.z;
            acc[i][3] += a[i] * wv.w;
        }
    }
#pragma unroll
    for (int i = 0; i < 8; i++) {
        int r = row0 + ty * 8 + i;
        if (r < NN)
            *(float4*)&Cp[r * 128 + colbase + tx * 4] =
                make_float4(acc[i][0], acc[i][1], acc[i][2], acc[i][3]);
    }
}

// ---- per-edge logit partial: leakyrelu + (log2e-scaled) att dot ----
__device__ __forceinline__ float logit_part(float4 xlv, float4 xrv, float4 attv) {
    float cx = xlv.x + xrv.x, cy = xlv.y + xrv.y, cz = xlv.z + xrv.z, cw = xlv.w + xrv.w;
    cx = fmaxf(cx, NEG * cx); cy = fmaxf(cy, NEG * cy);
    cz = fmaxf(cz, NEG * cz); cw = fmaxf(cw, NEG * cw);
    return cx * attv.x + cy * attv.y + cz * attv.z + cw * attv.w;
}

// ---------------- aggregation: warp/node, batched indices, exp2 softmax, inline fin ----------------
// lane l handles channels [l*4, l*4+4); lanes 0..15 = head 0, 16..31 = head 1.
__global__ void k_agg(const float* __restrict__ att, const float* __restrict__ bias,
                      const float* __restrict__ gw, const float* __restrict__ gb,
                      const float* __restrict__ gm) {
    __shared__ float ssum[64], ssq[64];
    __shared__ bool is_last;
    const unsigned FULL = 0xffffffffu;
    int tid = threadIdx.x;
    if (tid < 64) { ssum[tid] = 0.f; ssq[tid] = 0.f; }
    __syncthreads();

    int v = (blockIdx.x * 256 + tid) >> 5;   // 6250 blocks * 8 warps = 50000 exactly
    int lane = tid & 31;
    const float4* xl4 = (const float4*)g_xl;
    float4 xrv  = ((const float4*)g_xr)[v * 32 + lane];
    float4 attv = __ldg(&((const float4*)att)[lane]);
    attv.x *= L2E; attv.y *= L2E; attv.z *= L2E; attv.w *= L2E;   // exp -> exp2

    // self-loop: exp reference (a_self = 1)
    float4 xs = xl4[v * 32 + lane];
    float m = logit_part(xs, xrv, attv);
    m += __shfl_xor_sync(FULL, m, 8);
    m += __shfl_xor_sync(FULL, m, 4);
    m += __shfl_xor_sync(FULL, m, 2);
    m += __shfl_xor_sync(FULL, m, 1);

    float z = 1.f;
    float4 acc = xs;

    int e0 = __ldg(&g_rowptr[v]);
    int e1 = __ldg(&g_rowptr[v + 1]);
    int e = e0;
    while (e < e1) {
        int rem = e1 - e;
        int nb = rem < 32 ? rem : 32;
        // one coalesced load covers up to 32 edge indices for this warp
        int idx = __ldg(&g_csrsrc[e + (lane < nb ? lane : nb - 1)]);
        int i = 0;
        for (; i + 4 <= nb; i += 4) {
            int u0 = __shfl_sync(FULL, idx, i);
            int u1 = __shfl_sync(FULL, idx, i + 1);
            int u2 = __shfl_sync(FULL, idx, i + 2);
            int u3 = __shfl_sync(FULL, idx, i + 3);
            float4 x0 = __ldg(&xl4[u0 * 32 + lane]);
            float4 x1 = __ldg(&xl4[u1 * 32 + lane]);
            float4 x2 = __ldg(&xl4[u2 * 32 + lane]);
            float4 x3 = __ldg(&xl4[u3 * 32 + lane]);
            float p0 = logit_part(x0, xrv, attv);
            float p1 = logit_part(x1, xrv, attv);
            float p2 = logit_part(x2, xrv, attv);
            float p3 = logit_part(x3, xrv, attv);
            p0 += __shfl_xor_sync(FULL, p0, 8);
            p1 += __shfl_xor_sync(FULL, p1, 8);
            p2 += __shfl_xor_sync(FULL, p2, 8);
            p3 += __shfl_xor_sync(FULL, p3, 8);
            p0 += __shfl_xor_sync(FULL, p0, 4);
            p1 += __shfl_xor_sync(FULL, p1, 4);
            p2 += __shfl_xor_sync(FULL, p2, 4);
            p3 += __shfl_xor_sync(FULL, p3, 4);
            p0 += __shfl_xor_sync(FULL, p0, 2);
            p1 += __shfl_xor_sync(FULL, p1, 2);
            p2 += __shfl_xor_sync(FULL, p2, 2);
            p3 += __shfl_xor_sync(FULL, p3, 2);
            p0 += __shfl_xor_sync(FULL, p0, 1);
            p1 += __shfl_xor_sync(FULL, p1, 1);
            p2 += __shfl_xor_sync(FULL, p2, 1);
            p3 += __shfl_xor_sync(FULL, p3, 1);
            float a0 = exp2f(p0 - m);
            float a1 = exp2f(p1 - m);
            float a2 = exp2f(p2 - m);
            float a3 = exp2f(p3 - m);
            z += (a0 + a1) + (a2 + a3);
            acc.x += a0 * x0.x + a1 * x1.x + a2 * x2.x + a3 * x3.x;
            acc.y += a0 * x0.y + a1 * x1.y + a2 * x2.y + a3 * x3.y;
            acc.z += a0 * x0.z + a1 * x1.z + a2 * x2.z + a3 * x3.z;
            acc.w += a0 * x0.w + a1 * x1.w + a2 * x2.w + a3 * x3.w;
        }
        for (; i < nb; i++) {
            int u0 = __shfl_sync(FULL, idx, i);
            float4 x0 = __ldg(&xl4[u0 * 32 + lane]);
            float p0 = logit_part(x0, xrv, attv);
            p0 += __shfl_xor_sync(FULL, p0, 8);
            p0 += __shfl_xor_sync(FULL, p0, 4);
            p0 += __shfl_xor_sync(FULL, p0, 2);
            p0 += __shfl_xor_sync(FULL, p0, 1);
            float a0 = exp2f(p0 - m);
            z += a0;
            acc.x += a0 * x0.x; acc.y += a0 * x0.y;
            acc.z += a0 * x0.z; acc.w += a0 * x0.w;
        }
        e += nb;
    }

    float inv = 1.f / z;
    float4 r;
    r.x = acc.x * inv; r.y = acc.y * inv; r.z = acc.z * inv; r.w = acc.w * inv;
    // mean over heads: partner lane is lane^16
    r.x += __shfl_xor_sync(FULL, r.x, 16);
    r.y += __shfl_xor_sync(FULL, r.y, 16);
    r.z += __shfl_xor_sync(FULL, r.z, 16);
    r.w += __shfl_xor_sync(FULL, r.w, 16);
    if (lane < 16) {
        float4 b4 = __ldg(&((const float4*)bias)[lane]);
        float4 o;
        o.x = 0.5f * r.x + b4.x;
        o.y = 0.5f * r.y + b4.y;
        o.z = 0.5f * r.z + b4.z;
        o.w = 0.5f * r.w + b4.w;
        ((float4*)g_y)[v * 16 + lane] = o;
        int c = lane * 4;
        atomicAdd(&ssum[c + 0], o.x); atomicAdd(&ssq[c + 0], o.x * o.x);
        atomicAdd(&ssum[c + 1], o.y); atomicAdd(&ssq[c + 1], o.y * o.y);
        atomicAdd(&ssum[c + 2], o.z); atomicAdd(&ssq[c + 2], o.z * o.z);
        atomicAdd(&ssum[c + 3], o.w); atomicAdd(&ssq[c + 3], o.w * o.w);
    }
    __syncthreads();
    if (tid < 64) {
        atomicAdd(&g_sum[tid], ssum[tid]);
        atomicAdd(&g_sumsq[tid], ssq[tid]);
    }
    // last-arriving block computes the norm constants inline (replaces k_fin)
    if (tid == 0) {
        __threadfence();
        int n = atomicAdd(&g_done, 1);
        is_last = (n == AGG_BLOCKS - 1);
    }
    __syncthreads();
    if (is_last && tid < 64) {
        int c = tid;
        const float invn = 1.f / (float)NN;
        float mu  = g_sum[c] * invn;
        float ex2 = g_sumsq[c] * invn;
        float gmv = __ldg(&gm[c]);
        float var = ex2 - gmv * (2.f - gmv) * mu * mu;
        float A = __ldg(&gw[c]) * rsqrtf(var + EPSV);
        g_nA[c] = A;
        g_nB[c] = __ldg(&gb[c]) - A * gmv * mu;
        g_sum[c] = 0.f;
        g_sumsq[c] = 0.f;
        if (c == 0) g_done = 0;   // self-reset: graph-replay safe
    }
}

// ---------------- final apply (layer 3 output) ----------------
__global__ void k_apply3(float* __restrict__ xo) {
    int t = blockIdx.x * blockDim.x + threadIdx.x;
    int col = t & 63;
    xo[t] = fmaxf(g_y[t] * g_nA[col] + g_nB[col], 0.f);
}

// ---------------- launch (single stream, graph-capturable) ----------------
extern "C" void kernel_launch(void* const* d_in, const int* in_sizes, int n_in,
                              void* d_out, int out_size) {
    const float* x  = (const float*)d_in[0];
    const int*   ei = (const int*)d_in[1];
    const float *Wl[3], *Wr[3], *att[3], *bb[3], *gw[3], *gb[3], *gm[3];
    for (int i = 0; i < 3; i++) {
        int o = 2 + i * 7;
        Wl[i]  = (const float*)d_in[o + 0];
        Wr[i]  = (const float*)d_in[o + 1];
        att[i] = (const float*)d_in[o + 2];
        bb[i]  = (const float*)d_in[o + 3];
        gw[i]  = (const float*)d_in[o + 4];
        gb[i]  = (const float*)d_in[o + 5];
        gm[i]  = (const float*)d_in[o + 6];
    }
    const int* srcp = ei;
    const int* dstp = ei + EE;

    k_zero_all<<<(NN + 255) / 256, 256>>>();
    k_hist_gemm3<<<3125 + 6250, 256>>>(dstp, x, Wl[0], Wr[0]);   // hist ∥ layer-1 GEMM
    k_scan<<<1, 1024>>>();
    k_scatter<<<(EE / 4 + 255) / 256, 256>>>(srcp, dstp);

    dim3 ggemm((NN + 127) / 128, 4);

    // layer 1 (agg computes norm constants inline)
    k_agg<<<AGG_BLOCKS, 256>>>(att[0], bb[0], gw[0], gb[0], gm[0]);
    // layer 2
    k_gemm64<<<ggemm, 256>>>(Wl[1], Wr[1]);
    k_agg<<<AGG_BLOCKS, 256>>>(att[1], bb[1], gw[1], gb[1], gm[1]);
    // layer 3
    k_gemm64<<<ggemm, 256>>>(Wl[2], Wr[2]);
    k_agg<<<AGG_BLOCKS, 256>>>(att[2], bb[2], gw[2], gb[2], gm[2]);
    k_apply3<<<(NN * 64) / 256, 256>>>((float*)d_out);
}